// round 15
// baseline (speedup 1.0000x reference)
#include <cuda_runtime.h>
#include <cuda_fp16.h>
#include <math.h>
#include <stdint.h>

// ---------------- problem constants ----------------
#define NTOK   512
#define DDIM   768
#define MDIM   3072
#define NGRP   4
#define NEXP   8
#define NE_ALL 32
#define NASSIGN 2048      // NTOK * KG * KE
#define MCHUNK 128        // rows per GEMM chunk (M tile)
#define NCH    48
#define KSPLIT2 4         // fc2 split-K factor

// ---------------- scratch (device globals; no allocation) ----------------
__device__ __half g_xg[NASSIGN * DDIM];             // gathered x (fp16)
__device__ __half g_h [NASSIGN * MDIM];             // gelu(fc1)  (fp16)
__device__ float  g_yk[KSPLIT2][NASSIGN * DDIM];    // fc2 partial outputs
__device__ int    g_assign_expert[NASSIGN];
__device__ float  g_assign_w[NASSIGN];
__device__ int    g_pos[NASSIGN];
__device__ int    g_sorted[NASSIGN];
__device__ int    g_chunks[NCH * 3];                // (expert, row0, len)
__device__ int    g_nchunks;

// ---------------- PTX helpers (sm_80-compatible only) ----------------
__device__ __forceinline__ uint32_t smem_u32(const void* p) {
    uint32_t a;
    asm("{ .reg .u64 t; cvta.to.shared.u64 t, %1; cvt.u32.u64 %0, t; }" : "=r"(a) : "l"(p));
    return a;
}
// pack two f32 -> f16x2 register {lo=lo, hi=hi}
__device__ __forceinline__ uint32_t pack_h2(float lo, float hi) {
    uint32_t r;
    asm("cvt.rn.f16x2.f32 %0, %1, %2;" : "=r"(r) : "f"(hi), "f"(lo));
    return r;
}
__device__ __forceinline__ void mma_f16(float* c, const uint32_t* a, uint32_t b0, uint32_t b1) {
    asm volatile("mma.sync.aligned.m16n8k16.row.col.f32.f16.f16.f32 "
                 "{%0,%1,%2,%3}, {%4,%5,%6,%7}, {%8,%9}, {%0,%1,%2,%3};"
                 : "+f"(c[0]), "+f"(c[1]), "+f"(c[2]), "+f"(c[3])
                 : "r"(a[0]), "r"(a[1]), "r"(a[2]), "r"(a[3]), "r"(b0), "r"(b1));
}
// warp-collective 4x(8x8 b16) matrix load
__device__ __forceinline__ void ldmatrix_x4(uint32_t* d, uint32_t addr) {
    asm volatile("ldmatrix.sync.aligned.m8n8.x4.shared.b16 {%0,%1,%2,%3}, [%4];"
                 : "=r"(d[0]), "=r"(d[1]), "=r"(d[2]), "=r"(d[3]) : "r"(addr));
}
#define CP_ASYNC16(dst, src) \
    asm volatile("cp.async.cg.shared.global [%0], [%1], 16;" :: "r"(dst), "l"(src))
#define CP_COMMIT() asm volatile("cp.async.commit_group;" ::: "memory")
#define CP_WAIT1()  asm volatile("cp.async.wait_group 1;"  ::: "memory")

__device__ __forceinline__ float gelu_exact(float v) {
    return 0.5f * v * (1.0f + erff(v * 0.70710678118654752440f));
}

// ---------------- K1: routing (one warp per token, fp32) ----------------
__global__ void routing_kernel(const float* __restrict__ x,
                               const float* __restrict__ Wg,
                               const float* __restrict__ bg,
                               const float* __restrict__ Wge,
                               const float* __restrict__ bge) {
    int warp = threadIdx.x >> 5;
    int lane = threadIdx.x & 31;
    int n = blockIdx.x * 8 + warp;
    if (n >= NTOK) return;
    const float* xr = x + (size_t)n * DDIM;

    float ga[NGRP] = {0.f, 0.f, 0.f, 0.f};
    for (int d = lane; d < DDIM; d += 32) {
        float xv = xr[d];
        float4 wv = *reinterpret_cast<const float4*>(Wg + (size_t)d * NGRP);
        ga[0] += xv * wv.x; ga[1] += xv * wv.y;
        ga[2] += xv * wv.z; ga[3] += xv * wv.w;
    }
#pragma unroll
    for (int g = 0; g < NGRP; g++) {
#pragma unroll
        for (int o = 16; o; o >>= 1) ga[g] += __shfl_xor_sync(0xFFFFFFFFu, ga[g], o);
        ga[g] += bg[g];
    }
    int g0 = 0;
    for (int g = 1; g < NGRP; g++) if (ga[g] > ga[g0]) g0 = g;
    int g1 = -1; float best = -INFINITY;
    for (int g = 0; g < NGRP; g++) if (g != g0 && ga[g] > best) { best = ga[g]; g1 = g; }
    float t = expf(ga[g1] - ga[g0]);
    float gg0 = 1.0f / (1.0f + t);
    float gg1 = t * gg0;
    int   gs[2]  = {g0, g1};
    float ggs[2] = {gg0, gg1};

    for (int j = 0; j < 2; j++) {
        int g = gs[j];
        const float* Wb = Wge + (size_t)g * DDIM * NEXP;
        float ea[NEXP];
#pragma unroll
        for (int e = 0; e < NEXP; e++) ea[e] = 0.f;
        for (int d = lane; d < DDIM; d += 32) {
            float xv = xr[d];
            float4 w0 = *reinterpret_cast<const float4*>(Wb + (size_t)d * NEXP);
            float4 w1 = *reinterpret_cast<const float4*>(Wb + (size_t)d * NEXP + 4);
            ea[0] += xv * w0.x; ea[1] += xv * w0.y; ea[2] += xv * w0.z; ea[3] += xv * w0.w;
            ea[4] += xv * w1.x; ea[5] += xv * w1.y; ea[6] += xv * w1.z; ea[7] += xv * w1.w;
        }
#pragma unroll
        for (int e = 0; e < NEXP; e++) {
#pragma unroll
            for (int o = 16; o; o >>= 1) ea[e] += __shfl_xor_sync(0xFFFFFFFFu, ea[e], o);
            ea[e] += bge[g * NEXP + e];
        }
        int e0 = 0;
        for (int e = 1; e < NEXP; e++) if (ea[e] > ea[e0]) e0 = e;
        int e1 = -1; float b2v = -INFINITY;
        for (int e = 0; e < NEXP; e++) if (e != e0 && ea[e] > b2v) { b2v = ea[e]; e1 = e; }
        float te  = expf(ea[e1] - ea[e0]);
        float eg0 = 1.0f / (1.0f + te);
        float eg1 = te * eg0;
        if (lane == 0) {
            int a0 = n * 4 + j * 2;
            g_assign_expert[a0]     = g * NEXP + e0;
            g_assign_w[a0]          = ggs[j] * eg0;
            g_assign_expert[a0 + 1] = g * NEXP + e1;
            g_assign_w[a0 + 1]      = ggs[j] * eg1;
        }
    }
}

// ---------------- K2: counting sort + chunk worklist ----------------
__global__ void sort_kernel() {
    __shared__ int sc[NE_ALL];
    __shared__ int scur[NE_ALL];
    int tid = threadIdx.x;
    if (tid < NE_ALL) sc[tid] = 0;
    __syncthreads();
    for (int a = tid; a < NASSIGN; a += blockDim.x)
        atomicAdd(&sc[g_assign_expert[a]], 1);
    __syncthreads();
    if (tid == 0) {
        int off = 0, nc = 0;
        for (int e = 0; e < NE_ALL; e++) {
            scur[e] = off;
            int c = sc[e], st = off, o2 = 0;
            while (o2 < c) {
                int len = min(MCHUNK, c - o2);
                g_chunks[nc * 3 + 0] = e;
                g_chunks[nc * 3 + 1] = st + o2;
                g_chunks[nc * 3 + 2] = len;
                nc++; o2 += MCHUNK;
            }
            off += c;
        }
        g_nchunks = nc;
    }
    __syncthreads();
    for (int a = tid; a < NASSIGN; a += blockDim.x) {
        int e = g_assign_expert[a];
        int p = atomicAdd(&scur[e], 1);
        g_pos[a] = p;
        g_sorted[p] = a;
    }
}

// ---------------- K3: gather x rows (fp16 convert) ----------------
__global__ void gather_kernel(const float* __restrict__ x) {
    int p = blockIdx.x;
    int a = g_sorted[p];
    int n = a >> 2;
    int q = threadIdx.x;                       // cols 4q..4q+3
    float4 v = reinterpret_cast<const float4*>(x + (size_t)n * DDIM)[q];
    __half2* dst = reinterpret_cast<__half2*>(g_xg + (size_t)p * DDIM + q * 4);
    dst[0] = __floats2half2_rn(v.x, v.y);
    dst[1] = __floats2half2_rn(v.z, v.w);
}

// ---------------- K4/K5: unified fp16 expert GEMM ----------------
// CTA tile 128x64x32, 8 warps (2M x 4N), warp tile 64x16, m16n8k16 f16,
// 3-stage cp.async, 3 CTA/SM (32 acc/thread). A via ldmatrix.x4; B fp32 in
// smem packed to f16x2 at fragment load. mt-guards skip M padding.
template <bool FC1, int KSPL>
__global__ void __launch_bounds__(256, 3) moe_gemm(const float* __restrict__ W,
                                                   const float* __restrict__ bias) {
    constexpr int K   = FC1 ? DDIM : MDIM;    // logical K (elements)
    constexpr int NF  = FC1 ? MDIM : DDIM;
    constexpr int KQ  = K / KSPL;             // 768 both
    constexpr int BM = 128, BN = 64, BK = 32;
    constexpr int NKI = KQ / BK;              // 24
    constexpr int S   = 3;                    // pipeline stages
    constexpr int APADB = 80;                 // bytes per A row (40 halfs)
    constexpr int BPAD  = 68;                 // floats per B row
    constexpr int ABYTES = BM * APADB;        // 10240
    constexpr int BBYTES = BK * BPAD * 4;     // 8704

    int chunk = blockIdx.y;
    if (chunk >= g_nchunks) return;
    const int e    = g_chunks[chunk * 3 + 0];
    const int row0 = g_chunks[chunk * 3 + 1];
    const int len  = g_chunks[chunk * 3 + 2];
    const int n0   = blockIdx.x * BN;
    const int z    = KSPL > 1 ? blockIdx.z : 0;

    extern __shared__ char dsm[];
    char*  aS = dsm;                          // S stages of A (fp16)
    float* bS = reinterpret_cast<float*>(dsm + S * ABYTES);  // S stages of B (fp32)
    __shared__ float s_bias[BN];

    const uint32_t a_u32 = smem_u32(aS);
    const uint32_t b_u32 = smem_u32(bS);

    const int tid = threadIdx.x;
    const int wid = tid >> 5, lane = tid & 31;
    const int gid = lane >> 2, tig = lane & 3;
    const int M0w = (wid >> 2) * 64;
    const int N0w = (wid & 3) * 16;

    const __half* Aptr = (FC1 ? g_xg : g_h) + (size_t)row0 * K + (size_t)z * KQ;
    const float*  Bptr = W + (size_t)e * K * NF + (size_t)z * KQ * NF + n0;

    if (tid < BN) s_bias[tid] = (z == 0) ? bias[(size_t)e * NF + n0 + tid] : 0.f;
    __syncthreads();

    // cp.async mappings
    const int am = tid >> 1;                  // A row 0..127
    const int ac = (tid & 1) * 2;             // A 16B chunk base (0 or 2; +j)
    const int bk = tid >> 4;                  // B rows bk, bk+16
    const int bq = tid & 15;                  // B 16B chunk 0..15

    auto load_tile = [&](int t) {
        const int s = t % S;
        // A: 128 rows x 64B (32 halfs); 2 chunks of 16B per thread
        if (am < len) {
            const __half* arow = Aptr + (size_t)am * K + t * BK;
            uint32_t drow = a_u32 + (uint32_t)(s * ABYTES + am * APADB);
#pragma unroll
            for (int j = 0; j < 2; j++)
                CP_ASYNC16(drow + (ac + j) * 16u, arow + (ac + j) * 8);
        }
        // B: 32 rows x 256B (64 floats); 16 chunks/row; 2 rows per thread
#pragma unroll
        for (int j = 0; j < 2; j++) {
            int k = bk + 16 * j;
            const float* src = Bptr + (size_t)(t * BK + k) * NF + bq * 4;
            uint32_t dst = b_u32 + (uint32_t)(s * BBYTES + (k * BPAD + bq * 4) * 4);
            CP_ASYNC16(dst, src);
        }
    };

    float acc[4][2][4];
#pragma unroll
    for (int mt = 0; mt < 4; mt++)
#pragma unroll
        for (int nt = 0; nt < 2; nt++)
#pragma unroll
            for (int i = 0; i < 4; i++) acc[mt][nt][i] = 0.f;

    load_tile(0); CP_COMMIT();
    load_tile(1); CP_COMMIT();

    // live 16-row sub-tiles for this warp's 64-row band (0..4)
    const int nmt = min(4, max(0, (len - M0w + 15) >> 4));

    // ldmatrix per-lane offset: row = M0w + mt*16 + (lane&15),
    // k-half = (lane>>4)*16 bytes; per (mt,ks) add mt*16*APADB + ks*32 bytes
    const uint32_t a_lm_off = (uint32_t)(M0w + (lane & 15)) * APADB
                            + (uint32_t)(lane >> 4) * 16u;

    for (int t = 0; t < NKI; t++) {
        CP_WAIT1();
        __syncthreads();                      // stage t ready; stage (t+2)%S free
        if (t + 2 < NKI) load_tile(t + 2);
        CP_COMMIT();

        if (nmt > 0) {
            const int s = t % S;
            const uint32_t a_st = a_u32 + (uint32_t)(s * ABYTES) + a_lm_off;
            const float* Bsf = bS + s * (BBYTES / 4);
#pragma unroll
            for (int ks = 0; ks < 2; ks++) {          // two k16 steps per tile
                const int k0 = ks * 16;
                uint32_t a[4][4];
#pragma unroll
                for (int mt = 0; mt < 4; mt++) {
                    if (mt < nmt)
                        ldmatrix_x4(a[mt], a_st + (uint32_t)(mt * 16 * APADB + ks * 32));
                }
#pragma unroll
                for (int nt = 0; nt < 2; nt++) {
                    const int n = N0w + nt * 8 + gid;
                    const float* pb = Bsf + (size_t)(k0 + 2 * tig) * BPAD + n;
                    uint32_t b0 = pack_h2(pb[0],        pb[BPAD]);        // k, k+1
                    uint32_t b1 = pack_h2(pb[8 * BPAD], pb[9 * BPAD]);    // k+8, k+9
#pragma unroll
                    for (int mt = 0; mt < 4; mt++)
                        if (mt < nmt) mma_f16(acc[mt][nt], a[mt], b0, b1);
                }
            }
        }
    }

    if (nmt > 0) {
#pragma unroll
        for (int mt = 0; mt < 4; mt++) {
            if (mt < nmt) {
#pragma unroll
                for (int rr = 0; rr < 2; rr++) {
                    int row = M0w + mt * 16 + gid + 8 * rr;
                    if (row < len) {
#pragma unroll
                        for (int nt = 0; nt < 2; nt++) {
                            int col = N0w + nt * 8 + tig * 2;
                            float v0 = acc[mt][nt][2 * rr + 0] + s_bias[col];
                            float v1 = acc[mt][nt][2 * rr + 1] + s_bias[col + 1];
                            if (FC1) {
                                v0 = gelu_exact(v0);
                                v1 = gelu_exact(v1);
                                __half2* dst = reinterpret_cast<__half2*>(
                                    g_h + (size_t)(row0 + row) * NF + n0 + col);
                                *dst = __floats2half2_rn(v0, v1);
                            } else {
                                float* Crow = g_yk[z] + (size_t)(row0 + row) * NF + n0;
                                *reinterpret_cast<float2*>(Crow + col) = make_float2(v0, v1);
                            }
                        }
                    }
                }
            }
        }
    }
}

// ---------------- K6: weighted combine (sums KSPLIT2 partials) -----------
__global__ void combine_kernel(float* __restrict__ out) {
    int n = blockIdx.x;
    float w[4]; int p[4];
#pragma unroll
    for (int s = 0; s < 4; s++) {
        w[s] = g_assign_w[n * 4 + s];
        p[s] = g_pos[n * 4 + s];
    }
    int d = threadIdx.x * 4;
    float4 r = make_float4(0.f, 0.f, 0.f, 0.f);
#pragma unroll
    for (int s = 0; s < 4; s++) {
        float sx = 0.f, sy = 0.f, sz = 0.f, sw = 0.f;
#pragma unroll
        for (int z = 0; z < KSPLIT2; z++) {
            float4 v = *reinterpret_cast<const float4*>(g_yk[z] + (size_t)p[s] * DDIM + d);
            sx += v.x; sy += v.y; sz += v.z; sw += v.w;
        }
        r.x += w[s] * sx; r.y += w[s] * sy;
        r.z += w[s] * sz; r.w += w[s] * sw;
    }
    *reinterpret_cast<float4*>(out + (size_t)n * DDIM + d) = r;
}

// ---------------- launch ----------------
extern "C" void kernel_launch(void* const* d_in, const int* in_sizes, int n_in,
                              void* d_out, int out_size) {
    const float* x   = (const float*)d_in[0];
    const float* Wg  = (const float*)d_in[1];
    const float* bg  = (const float*)d_in[2];
    const float* Wge = (const float*)d_in[3];
    const float* bge = (const float*)d_in[4];
    const float* W1  = (const float*)d_in[5];
    const float* b1  = (const float*)d_in[6];
    const float* W2  = (const float*)d_in[7];
    const float* b2  = (const float*)d_in[8];
    float* out = (float*)d_out;

    // 3 stages * (128*80 + 32*68*4) bytes = 56832 B  (3 CTA/SM)
    const int dyn = 3 * (128 * 80 + 32 * 68 * 4);
    cudaFuncSetAttribute((const void*)moe_gemm<true, 1>,
                         cudaFuncAttributeMaxDynamicSharedMemorySize, dyn);
    cudaFuncSetAttribute((const void*)moe_gemm<false, KSPLIT2>,
                         cudaFuncAttributeMaxDynamicSharedMemorySize, dyn);

    routing_kernel<<<64, 256>>>(x, Wg, bg, Wge, bge);
    sort_kernel<<<1, 256>>>();
    gather_kernel<<<NASSIGN, 192>>>(x);
    moe_gemm<true, 1><<<dim3(MDIM / 64, NCH), 256, dyn>>>(W1, b1);
    moe_gemm<false, KSPLIT2><<<dim3(DDIM / 64, NCH, KSPLIT2), 256, dyn>>>(W2, b2);
    combine_kernel<<<NTOK, 192>>>(out);
}

// round 16
// speedup vs baseline: 1.0305x; 1.0305x over previous
#include <cuda_runtime.h>
#include <cuda_fp16.h>
#include <math.h>
#include <stdint.h>

// ---------------- problem constants ----------------
#define NTOK   512
#define DDIM   768
#define MDIM   3072
#define NGRP   4
#define NEXP   8
#define NE_ALL 32
#define NASSIGN 2048      // NTOK * KG * KE
#define MCHUNK 128        // rows per GEMM chunk (M tile)
#define NCH    48
#define KSPLIT2 4         // fc2 split-K factor

// ---------------- scratch (device globals; no allocation) ----------------
__device__ __half g_xg[NASSIGN * DDIM];             // gathered x (fp16)
__device__ __half g_h [NASSIGN * MDIM];             // gelu(fc1)  (fp16)
__device__ float  g_yk[KSPLIT2][NASSIGN * DDIM];    // fc2 partial outputs
__device__ int    g_assign_expert[NASSIGN];
__device__ float  g_assign_w[NASSIGN];
__device__ int    g_pos[NASSIGN];
__device__ int    g_sorted[NASSIGN];
__device__ int    g_chunks[NCH * 3];                // (expert, row0, len)
__device__ int    g_nchunks;
__device__ int    g_ticket;                         // routing-CTA completion ticket

// ---------------- PTX helpers (sm_80-compatible only) ----------------
__device__ __forceinline__ uint32_t smem_u32(const void* p) {
    uint32_t a;
    asm("{ .reg .u64 t; cvta.to.shared.u64 t, %1; cvt.u32.u64 %0, t; }" : "=r"(a) : "l"(p));
    return a;
}
// pack two f32 -> f16x2 register {lo=lo, hi=hi}
__device__ __forceinline__ uint32_t pack_h2(float lo, float hi) {
    uint32_t r;
    asm("cvt.rn.f16x2.f32 %0, %1, %2;" : "=r"(r) : "f"(hi), "f"(lo));
    return r;
}
__device__ __forceinline__ void mma_f16(float* c, const uint32_t* a, uint32_t b0, uint32_t b1) {
    asm volatile("mma.sync.aligned.m16n8k16.row.col.f32.f16.f16.f32 "
                 "{%0,%1,%2,%3}, {%4,%5,%6,%7}, {%8,%9}, {%0,%1,%2,%3};"
                 : "+f"(c[0]), "+f"(c[1]), "+f"(c[2]), "+f"(c[3])
                 : "r"(a[0]), "r"(a[1]), "r"(a[2]), "r"(a[3]), "r"(b0), "r"(b1));
}
// warp-collective 4x(8x8 b16) matrix load
__device__ __forceinline__ void ldmatrix_x4(uint32_t* d, uint32_t addr) {
    asm volatile("ldmatrix.sync.aligned.m8n8.x4.shared.b16 {%0,%1,%2,%3}, [%4];"
                 : "=r"(d[0]), "=r"(d[1]), "=r"(d[2]), "=r"(d[3]) : "r"(addr));
}
#define CP_ASYNC16(dst, src) \
    asm volatile("cp.async.cg.shared.global [%0], [%1], 16;" :: "r"(dst), "l"(src))
#define CP_COMMIT() asm volatile("cp.async.commit_group;" ::: "memory")
#define CP_WAIT2()  asm volatile("cp.async.wait_group 2;"  ::: "memory")

__device__ __forceinline__ float gelu_exact(float v) {
    return 0.5f * v * (1.0f + erff(v * 0.70710678118654752440f));
}

// ---------------- K1: routing (one warp per token) + fused sort ----------
// All 64 CTAs compute routing; the LAST CTA to finish (ticket==63) runs the
// counting sort + chunk worklist inline (threadfence-reduction pattern).
__global__ void routing_sort_kernel(const float* __restrict__ x,
                                    const float* __restrict__ Wg,
                                    const float* __restrict__ bg,
                                    const float* __restrict__ Wge,
                                    const float* __restrict__ bge) {
    int warp = threadIdx.x >> 5;
    int lane = threadIdx.x & 31;
    int n = blockIdx.x * 8 + warp;          // grid 64 x 8 warps = 512 = NTOK
    const float* xr = x + (size_t)n * DDIM;

    float ga[NGRP] = {0.f, 0.f, 0.f, 0.f};
    for (int d = lane; d < DDIM; d += 32) {
        float xv = xr[d];
        float4 wv = *reinterpret_cast<const float4*>(Wg + (size_t)d * NGRP);
        ga[0] += xv * wv.x; ga[1] += xv * wv.y;
        ga[2] += xv * wv.z; ga[3] += xv * wv.w;
    }
#pragma unroll
    for (int g = 0; g < NGRP; g++) {
#pragma unroll
        for (int o = 16; o; o >>= 1) ga[g] += __shfl_xor_sync(0xFFFFFFFFu, ga[g], o);
        ga[g] += bg[g];
    }
    int g0 = 0;
    for (int g = 1; g < NGRP; g++) if (ga[g] > ga[g0]) g0 = g;
    int g1 = -1; float best = -INFINITY;
    for (int g = 0; g < NGRP; g++) if (g != g0 && ga[g] > best) { best = ga[g]; g1 = g; }
    float t = expf(ga[g1] - ga[g0]);
    float gg0 = 1.0f / (1.0f + t);
    float gg1 = t * gg0;
    int   gs[2]  = {g0, g1};
    float ggs[2] = {gg0, gg1};

    for (int j = 0; j < 2; j++) {
        int g = gs[j];
        const float* Wb = Wge + (size_t)g * DDIM * NEXP;
        float ea[NEXP];
#pragma unroll
        for (int e = 0; e < NEXP; e++) ea[e] = 0.f;
        for (int d = lane; d < DDIM; d += 32) {
            float xv = xr[d];
            float4 w0 = *reinterpret_cast<const float4*>(Wb + (size_t)d * NEXP);
            float4 w1 = *reinterpret_cast<const float4*>(Wb + (size_t)d * NEXP + 4);
            ea[0] += xv * w0.x; ea[1] += xv * w0.y; ea[2] += xv * w0.z; ea[3] += xv * w0.w;
            ea[4] += xv * w1.x; ea[5] += xv * w1.y; ea[6] += xv * w1.z; ea[7] += xv * w1.w;
        }
#pragma unroll
        for (int e = 0; e < NEXP; e++) {
#pragma unroll
            for (int o = 16; o; o >>= 1) ea[e] += __shfl_xor_sync(0xFFFFFFFFu, ea[e], o);
            ea[e] += bge[g * NEXP + e];
        }
        int e0 = 0;
        for (int e = 1; e < NEXP; e++) if (ea[e] > ea[e0]) e0 = e;
        int e1 = -1; float b2v = -INFINITY;
        for (int e = 0; e < NEXP; e++) if (e != e0 && ea[e] > b2v) { b2v = ea[e]; e1 = e; }
        float te  = expf(ea[e1] - ea[e0]);
        float eg0 = 1.0f / (1.0f + te);
        float eg1 = te * eg0;
        if (lane == 0) {
            int a0 = n * 4 + j * 2;
            g_assign_expert[a0]     = g * NEXP + e0;
            g_assign_w[a0]          = ggs[j] * eg0;
            g_assign_expert[a0 + 1] = g * NEXP + e1;
            g_assign_w[a0 + 1]      = ggs[j] * eg1;
        }
    }

    // ---- ticket: last CTA performs the sort ----
    __shared__ int s_last;
    __syncthreads();
    if (threadIdx.x == 0) {
        __threadfence();                      // publish this CTA's assignments
        int tk = atomicAdd(&g_ticket, 1);
        s_last = (tk == gridDim.x - 1);
    }
    __syncthreads();
    if (!s_last) return;
    __threadfence();                          // acquire all CTAs' writes

    __shared__ int sc[NE_ALL];
    __shared__ int scur[NE_ALL];
    int tid = threadIdx.x;
    if (tid < NE_ALL) sc[tid] = 0;
    __syncthreads();
    for (int a = tid; a < NASSIGN; a += blockDim.x)
        atomicAdd(&sc[g_assign_expert[a]], 1);
    __syncthreads();
    if (tid == 0) {
        int off = 0, nc = 0;
        for (int e = 0; e < NE_ALL; e++) {
            scur[e] = off;
            int c = sc[e], st = off, o2 = 0;
            while (o2 < c) {
                int len = min(MCHUNK, c - o2);
                g_chunks[nc * 3 + 0] = e;
                g_chunks[nc * 3 + 1] = st + o2;
                g_chunks[nc * 3 + 2] = len;
                nc++; o2 += MCHUNK;
            }
            off += c;
        }
        g_nchunks = nc;
    }
    __syncthreads();
    for (int a = tid; a < NASSIGN; a += blockDim.x) {
        int e = g_assign_expert[a];
        int p = atomicAdd(&scur[e], 1);
        g_pos[a] = p;
        g_sorted[p] = a;
    }
}

// ---------------- K3: gather x rows (fp16 convert) ----------------
__global__ void gather_kernel(const float* __restrict__ x) {
    int p = blockIdx.x;
    int a = g_sorted[p];
    int n = a >> 2;
    int q = threadIdx.x;                       // cols 4q..4q+3
    float4 v = reinterpret_cast<const float4*>(x + (size_t)n * DDIM)[q];
    __half2* dst = reinterpret_cast<__half2*>(g_xg + (size_t)p * DDIM + q * 4);
    dst[0] = __floats2half2_rn(v.x, v.y);
    dst[1] = __floats2half2_rn(v.z, v.w);
}

// ---------------- K4/K5: unified fp16 expert GEMM (R14 config) -----------
// CTA tile 128x128x32, 8 warps (2M x 4N), warp tile 64x32, m16n8k16 f16,
// 4-stage cp.async, 2 CTA/SM. A fragments via ldmatrix.x4; B fp32 in smem,
// packed to f16x2 at fragment load. mt-guards skip M padding.
template <bool FC1, int KSPL>
__global__ void __launch_bounds__(256, 2) moe_gemm(const float* __restrict__ W,
                                                   const float* __restrict__ bias) {
    constexpr int K   = FC1 ? DDIM : MDIM;    // logical K (elements)
    constexpr int NF  = FC1 ? MDIM : DDIM;
    constexpr int KQ  = K / KSPL;             // 768 both
    constexpr int BM = 128, BN = 128, BK = 32;
    constexpr int NKI = KQ / BK;              // 24
    constexpr int S   = 4;                    // pipeline stages
    constexpr int APADB = 80;                 // bytes per A row (40 halfs)
    constexpr int BPAD  = 132;                // floats per B row
    constexpr int ABYTES = BM * APADB;        // 10240
    constexpr int BBYTES = BK * BPAD * 4;     // 16896

    int chunk = blockIdx.y;
    if (chunk >= g_nchunks) return;
    const int e    = g_chunks[chunk * 3 + 0];
    const int row0 = g_chunks[chunk * 3 + 1];
    const int len  = g_chunks[chunk * 3 + 2];
    const int n0   = blockIdx.x * BN;
    const int z    = KSPL > 1 ? blockIdx.z : 0;

    extern __shared__ char dsm[];
    char*  aS = dsm;                          // S stages of A (fp16)
    float* bS = reinterpret_cast<float*>(dsm + S * ABYTES);  // S stages of B (fp32)
    __shared__ float s_bias[BN];

    const uint32_t a_u32 = smem_u32(aS);
    const uint32_t b_u32 = smem_u32(bS);

    const int tid = threadIdx.x;
    const int wid = tid >> 5, lane = tid & 31;
    const int gid = lane >> 2, tig = lane & 3;
    const int M0w = (wid >> 2) * 64;
    const int N0w = (wid & 3) * 32;

    const __half* Aptr = (FC1 ? g_xg : g_h) + (size_t)row0 * K + (size_t)z * KQ;
    const float*  Bptr = W + (size_t)e * K * NF + (size_t)z * KQ * NF + n0;

    if (tid < BN) s_bias[tid] = (z == 0) ? bias[(size_t)e * NF + n0 + tid] : 0.f;
    __syncthreads();

    // cp.async mappings
    const int am = tid >> 1;                  // A row 0..127
    const int ac = (tid & 1) * 2;             // A 16B chunk base (0 or 2; +j)
    const int bk = tid >> 5, bq = tid & 31;   // B rows bk+8j, 16B chunk bq

    auto load_tile = [&](int t) {
        const int s = t % S;
        // A: 128 rows x 64B (32 halfs); 2 chunks of 16B per thread
        if (am < len) {
            const __half* arow = Aptr + (size_t)am * K + t * BK;
            uint32_t drow = a_u32 + (uint32_t)(s * ABYTES + am * APADB);
#pragma unroll
            for (int j = 0; j < 2; j++)
                CP_ASYNC16(drow + (ac + j) * 16u, arow + (ac + j) * 8);
        }
        // B: 32 rows x 512B; 4 chunks of 16B per thread
#pragma unroll
        for (int j = 0; j < 4; j++) {
            int k = bk + 8 * j;
            const float* src = Bptr + (size_t)(t * BK + k) * NF + bq * 4;
            uint32_t dst = b_u32 + (uint32_t)(s * BBYTES + (k * BPAD + bq * 4) * 4);
            CP_ASYNC16(dst, src);
        }
    };

    float acc[4][4][4];
#pragma unroll
    for (int mt = 0; mt < 4; mt++)
#pragma unroll
        for (int nt = 0; nt < 4; nt++)
#pragma unroll
            for (int i = 0; i < 4; i++) acc[mt][nt][i] = 0.f;

    load_tile(0); CP_COMMIT();
    load_tile(1); CP_COMMIT();
    load_tile(2); CP_COMMIT();

    // live 16-row sub-tiles for this warp's 64-row band (0..4)
    const int nmt = min(4, max(0, (len - M0w + 15) >> 4));

    // ldmatrix per-lane offset: row = M0w + mt*16 + (lane&15),
    // k-half = (lane>>4)*16 bytes; per (mt,ks) add mt*16*APADB + ks*32 bytes
    const uint32_t a_lm_off = (uint32_t)(M0w + (lane & 15)) * APADB
                            + (uint32_t)(lane >> 4) * 16u;

    for (int t = 0; t < NKI; t++) {
        CP_WAIT2();
        __syncthreads();                      // stage t ready; stage (t+3)%S free
        if (t + 3 < NKI) load_tile(t + 3);
        CP_COMMIT();

        if (nmt > 0) {
            const int s = t % S;
            const uint32_t a_st = a_u32 + (uint32_t)(s * ABYTES) + a_lm_off;
            const float* Bsf = bS + s * (BBYTES / 4);
#pragma unroll
            for (int ks = 0; ks < 2; ks++) {          // two k16 steps per tile
                const int k0 = ks * 16;
                uint32_t a[4][4];
#pragma unroll
                for (int mt = 0; mt < 4; mt++) {
                    if (mt < nmt)
                        ldmatrix_x4(a[mt], a_st + (uint32_t)(mt * 16 * APADB + ks * 32));
                }
#pragma unroll
                for (int nt = 0; nt < 4; nt++) {
                    const int n = N0w + nt * 8 + gid;
                    const float* pb = Bsf + (size_t)(k0 + 2 * tig) * BPAD + n;
                    uint32_t b0 = pack_h2(pb[0],        pb[BPAD]);        // k, k+1
                    uint32_t b1 = pack_h2(pb[8 * BPAD], pb[9 * BPAD]);    // k+8, k+9
#pragma unroll
                    for (int mt = 0; mt < 4; mt++)
                        if (mt < nmt) mma_f16(acc[mt][nt], a[mt], b0, b1);
                }
            }
        }
    }

    if (nmt > 0) {
#pragma unroll
        for (int mt = 0; mt < 4; mt++) {
            if (mt < nmt) {
#pragma unroll
                for (int rr = 0; rr < 2; rr++) {
                    int row = M0w + mt * 16 + gid + 8 * rr;
                    if (row < len) {
#pragma unroll
                        for (int nt = 0; nt < 4; nt++) {
                            int col = N0w + nt * 8 + tig * 2;
                            float v0 = acc[mt][nt][2 * rr + 0] + s_bias[col];
                            float v1 = acc[mt][nt][2 * rr + 1] + s_bias[col + 1];
                            if (FC1) {
                                v0 = gelu_exact(v0);
                                v1 = gelu_exact(v1);
                                __half2* dst = reinterpret_cast<__half2*>(
                                    g_h + (size_t)(row0 + row) * NF + n0 + col);
                                *dst = __floats2half2_rn(v0, v1);
                            } else {
                                float* Crow = g_yk[z] + (size_t)(row0 + row) * NF + n0;
                                *reinterpret_cast<float2*>(Crow + col) = make_float2(v0, v1);
                            }
                        }
                    }
                }
            }
        }
    }
}

// ---------------- K6: weighted combine (sums KSPLIT2 partials) -----------
__global__ void combine_kernel(float* __restrict__ out) {
    int n = blockIdx.x;
    float w[4]; int p[4];
#pragma unroll
    for (int s = 0; s < 4; s++) {
        w[s] = g_assign_w[n * 4 + s];
        p[s] = g_pos[n * 4 + s];
    }
    int d = threadIdx.x * 4;
    float4 r = make_float4(0.f, 0.f, 0.f, 0.f);
#pragma unroll
    for (int s = 0; s < 4; s++) {
        float sx = 0.f, sy = 0.f, sz = 0.f, sw = 0.f;
#pragma unroll
        for (int z = 0; z < KSPLIT2; z++) {
            float4 v = *reinterpret_cast<const float4*>(g_yk[z] + (size_t)p[s] * DDIM + d);
            sx += v.x; sy += v.y; sz += v.z; sw += v.w;
        }
        r.x += w[s] * sx; r.y += w[s] * sy;
        r.z += w[s] * sz; r.w += w[s] * sw;
    }
    *reinterpret_cast<float4*>(out + (size_t)n * DDIM + d) = r;
}

// ---------------- launch ----------------
extern "C" void kernel_launch(void* const* d_in, const int* in_sizes, int n_in,
                              void* d_out, int out_size) {
    const float* x   = (const float*)d_in[0];
    const float* Wg  = (const float*)d_in[1];
    const float* bg  = (const float*)d_in[2];
    const float* Wge = (const float*)d_in[3];
    const float* bge = (const float*)d_in[4];
    const float* W1  = (const float*)d_in[5];
    const float* b1  = (const float*)d_in[6];
    const float* W2  = (const float*)d_in[7];
    const float* b2  = (const float*)d_in[8];
    float* out = (float*)d_out;

    // 4 stages * (128*80 + 32*132*4) bytes = 108544 B
    const int dyn = 4 * (128 * 80 + 32 * 132 * 4);
    cudaFuncSetAttribute((const void*)moe_gemm<true, 1>,
                         cudaFuncAttributeMaxDynamicSharedMemorySize, dyn);
    cudaFuncSetAttribute((const void*)moe_gemm<false, KSPLIT2>,
                         cudaFuncAttributeMaxDynamicSharedMemorySize, dyn);

    // reset the routing-completion ticket (graph-capturable memset node)
    void* tk = nullptr;
    cudaGetSymbolAddress(&tk, g_ticket);
    cudaMemsetAsync(tk, 0, sizeof(int));

    routing_sort_kernel<<<64, 256>>>(x, Wg, bg, Wge, bge);
    gather_kernel<<<NASSIGN, 192>>>(x);
    moe_gemm<true, 1><<<dim3(MDIM / 128, NCH), 256, dyn>>>(W1, b1);
    moe_gemm<false, KSPLIT2><<<dim3(DDIM / 128, NCH, KSPLIT2), 256, dyn>>>(W2, b2);
    combine_kernel<<<NTOK, 192>>>(out);
}